// round 3
// baseline (speedup 1.0000x reference)
#include <cuda_runtime.h>
#include <cuda_fp16.h>
#include <cstdint>

#define B_   128
#define T_   256
#define K_   256
#define NTH  512
#define LOG2E 1.4426950408889634f
#define LN2   0.6931471805599453f
#define NEG_INF (-1e30f)

__global__ __launch_bounds__(NTH, 1)
void crf_loss_kernel(const float* __restrict__ feats,   // [B,T,K]
                     const float* __restrict__ trans,   // [K,K]
                     const int*   __restrict__ tags,    // [B,T]
                     const int*   __restrict__ lens,    // [B]
                     float*       __restrict__ out)     // [B]
{
    __shared__ __align__(16) __half ebuf[2][K_];  // double-buffered scaled exp(state)
    __shared__ int   gbuf[2];                     // double-buffered log2-normalizer
    __shared__ float f00sh;
    __shared__ float st[K_];                      // final log-domain state
    __shared__ float red[16];

    const int tid  = threadIdx.x;
    const int lane = tid & 31;
    const int w    = tid >> 5;            // 16 warps
    const int to   = (w << 4) | (lane & 15);
    const int h    = lane >> 4;           // from-half (same warp as partner!)
    const int b    = blockIdx.x;
    const int rot  = h * 2;               // bank-group offset for h=1 chunk reads
    const int cbase = h * 16;

    // ---- ET in registers: ET2[4i+j] pairs (exp tr[f][to], exp tr[f+1][to]) ----
    // chunk order matches the rotated es-read order below.
    __half2 ET2[64];
    #pragma unroll
    for (int i = 0; i < 16; ++i) {
        int c = ((i + rot) & 15) + cbase;          // es 8-half chunk index
        #pragma unroll
        for (int j = 0; j < 4; ++j) {
            int f0 = 8 * c + 2 * j;
            float e0 = __expf(__ldg(trans + (size_t)f0       * K_ + to));
            float e1 = __expf(__ldg(trans + (size_t)(f0 + 1) * K_ + to));
            ET2[4 * i + j] = __floats2half2_rn(e0, e1);
        }
    }

    const int len = lens[b];
    const float* fb = feats + (size_t)b * T_ * K_;

    // ---- init: es_0 = exp2(f0*log2e - g0), C = g0 ----
    float f0 = fb[to];
    if (tid == 0) f00sh = f0;
    __syncthreads();
    int   g0 = __float2int_rd(f00sh * LOG2E) + 14;   // es_0[0] ~ 2^-14
    float v  = exp2f(f0 * LOG2E - (float)g0);        // fp32 scaled state
    int   C  = g0;                                    // exact integer log2 offset
    if (h == 0) {
        ebuf[0][to] = __float2half_rn(v);
        if (to == 0) gbuf[0] = ((__float_as_int(v) >> 23) & 255) - 113; // exp+14
    }
    float fv = (len > 1) ? fb[K_ + to] : 0.f;        // prefetch t=1 emissions
    __syncthreads();

    // ---- forward recurrence: one barrier per step, no MUFU on serial path ----
    for (int t = 1; t < len; ++t) {
        const int p = (t - 1) & 1;
        int g = gbuf[p];
        C += g;
        float efv = exp2f(fv * LOG2E - (float)g);    // parallel with matvec
        int   tn  = (t + 1 < len) ? (t + 1) : (len - 1);
        float fvn = fb[(size_t)tn * K_ + to];        // prefetch next emissions

        // matvec half: sum over my 128 from-values
        const uint4* ep = reinterpret_cast<const uint4*>(ebuf[p]);
        __half2 zz = __float2half2_rn(0.f);
        __half2 a0 = zz, a1 = zz, a2 = zz, a3 = zz;
        #pragma unroll
        for (int i = 0; i < 16; ++i) {
            uint4 q = ep[((i + rot) & 15) + cbase];  // broadcast, conflict-free
            a0 = __hfma2(ET2[4 * i + 0], *reinterpret_cast<__half2*>(&q.x), a0);
            a1 = __hfma2(ET2[4 * i + 1], *reinterpret_cast<__half2*>(&q.y), a1);
            a2 = __hfma2(ET2[4 * i + 2], *reinterpret_cast<__half2*>(&q.z), a2);
            a3 = __hfma2(ET2[4 * i + 3], *reinterpret_cast<__half2*>(&q.w), a3);
        }
        float2 c0 = __half22float2(a0), c1 = __half22float2(a1);
        float2 c2 = __half22float2(a2), c3 = __half22float2(a3);
        float s = ((c0.x + c0.y) + (c1.x + c1.y)) + ((c2.x + c2.y) + (c3.x + c3.y));
        s += __shfl_xor_sync(0xffffffffu, s, 16);    // combine the two halves

        v = s * efv;                                  // new scaled state (fp32)
        if (h == 0) {
            ebuf[t & 1][to] = __float2half_rn(v);
            if (to == 0)                              // next normalizer: exp(v)+14
                gbuf[t & 1] = ((__float_as_int(v) >> 23) & 255) - 113;
        }
        fv = fvn;
        __syncthreads();
    }

    // ---- recover log-domain state, then forward = logsumexp ----
    if (h == 0) st[to] = (log2f(v) + (float)C) * LN2;
    __syncthreads();
    float state = (tid < K_) ? st[tid] : NEG_INF;

    float x = state;
    #pragma unroll
    for (int o = 16; o > 0; o >>= 1)
        x = fmaxf(x, __shfl_xor_sync(0xffffffffu, x, o));
    if (lane == 0) red[w] = x;
    __syncthreads();
    float bm = red[0];
    #pragma unroll
    for (int i = 1; i < 16; ++i) bm = fmaxf(bm, red[i]);
    __syncthreads();

    float e = (tid < K_) ? __expf(state - bm) : 0.f;
    #pragma unroll
    for (int o = 16; o > 0; o >>= 1)
        e += __shfl_xor_sync(0xffffffffu, e, o);
    if (lane == 0) red[w] = e;
    __syncthreads();
    float ssum = red[0];
    #pragma unroll
    for (int i = 1; i < 16; ++i) ssum += red[i];
    float forward = bm + __logf(ssum);
    __syncthreads();

    // ---- gold path score: thread tid handles timestep tid ----
    float u = 0.f;
    if (tid < len) {
        int tg = tags[b * T_ + tid];
        u = fb[(size_t)tid * K_ + tg];
        if (tid + 1 < len) {
            int tg2 = tags[b * T_ + tid + 1];
            u += __ldg(trans + (size_t)tg * K_ + tg2);
        }
    }
    #pragma unroll
    for (int o = 16; o > 0; o >>= 1)
        u += __shfl_xor_sync(0xffffffffu, u, o);
    if (lane == 0) red[w] = u;
    __syncthreads();
    if (tid == 0) {
        float us = red[0];
        #pragma unroll
        for (int i = 1; i < 16; ++i) us += red[i];
        out[b] = forward - us;
    }
}

extern "C" void kernel_launch(void* const* d_in, const int* in_sizes, int n_in,
                              void* d_out, int out_size) {
    const float* feats = (const float*)d_in[0];
    const float* trans = (const float*)d_in[1];
    const int*   tags  = (const int*)d_in[2];
    const int*   lens  = (const int*)d_in[3];
    float*       out   = (float*)d_out;

    crf_loss_kernel<<<B_, NTH>>>(feats, trans, tags, lens, out);
}